// round 2
// baseline (speedup 1.0000x reference)
#include <cuda_runtime.h>
#include <math.h>
#include <stdint.h>

// Problem constants (fixed by the reference)
#define T_LEN 128
#define B_ENV 4096
#define N_TOT (T_LEN * B_ENV)   // 524288
#define HID   128
#define FEAT  96
#define NA    6

// ---------------------------------------------------------------------------
// Scratch (device globals — no runtime allocation allowed)
// ---------------------------------------------------------------------------
__device__ float g_b0[(size_t)N_TOT * 256];   // 512 MB ping
__device__ float g_b1[(size_t)N_TOT * 256];   // 512 MB pong
__device__ float g_feat[(size_t)N_TOT * 96];  // 192 MB concat features
__device__ float g_gx[(size_t)N_TOT * 512];   // 1 GB  precomputed x-gates
__device__ uint32_t g_bperm[262144];          // 1 MB  permuted TF32 weights

__device__ __forceinline__ float sigf(float x) { return 1.f / (1.f + expf(-x)); }

__device__ __forceinline__ uint32_t f2tf32(float v) {
    uint32_t t;
    asm("cvt.rna.tf32.f32 %0, %1;" : "=r"(t) : "f"(v));
    return t;
}

// ---------------------------------------------------------------------------
// Pre-permute B into fragment-order TF32 layout.
// For column-block cb (BN cols) and k-chunk c (32 k), layout:
//   out[((cb*nChunks)+c)*BN*32 + n*32 + kt*8 + pos],  pos = kperm(k&7)
//   kperm(k) = ((k&3)<<1) | ((k>>2)&1)   (pairs k, k+4 adjacent)
// TRANSB: B stored [N,K] row-major; else [K,N] row-major.
// ---------------------------------------------------------------------------
template <bool TRANSB>
__global__ void bperm_kernel(const float* __restrict__ B, uint32_t* __restrict__ out,
                             int N, int K, int BN, int nChunks)
{
    int idx = blockIdx.x * blockDim.x + threadIdx.x;
    int total = N * 32 * nChunks;
    if (idx >= total) return;
    int off = idx & 31;            // kt*8 + pos
    int n   = (idx >> 5) % BN;
    int rem = (idx >> 5) / BN;
    int c   = rem % nChunks;
    int cb  = rem / nChunks;
    int kt  = off >> 3, pos = off & 7;
    int kl  = kt * 8 + ((pos >> 1) | ((pos & 1) << 2));  // inverse kperm
    int gk  = c * 32 + kl;
    int gn  = cb * BN + n;
    float v = 0.f;
    if (gk < K)
        v = TRANSB ? B[(size_t)gn * K + gk] : B[(size_t)gk * N + gn];
    out[(size_t)((cb * nChunks) + c) * BN * 32 + n * 32 + off] = f2tf32(v);
}

// ---------------------------------------------------------------------------
// TF32 tensor-core GEMM: C[M,N] = act(A[M,K]*aScale @ B + bias (+bias2))
// BM=128, BN template (128 or 32), BK=32, 256 threads = 8 warps.
// Warp grid 4(M) x 2(N): warp tile 32 x (BN/2). mma m16n8k8.
// A staged through SMEM (stride-40 rows, kperm order) -> conflict-free LDS.64.
// B read from pre-permuted global (Bp) -> trivial conflict-free copy.
// ---------------------------------------------------------------------------
template <int BN, bool RELU>
__global__ __launch_bounds__(256) void gemm_tf32(
    const float* __restrict__ A, const uint32_t* __restrict__ Bp,
    const float* __restrict__ bias, const float* __restrict__ bias2,
    float* __restrict__ C, int K, int nChunks, float aScale, int ldc, int coff)
{
    constexpr int WN = BN / 2;     // warp N-tile
    constexpr int NT = WN / 8;     // n8 tiles per warp
    __shared__ __align__(16) uint32_t As[128 * 40];
    __shared__ __align__(16) uint32_t Bs[BN * 40];

    const int tid  = threadIdx.x;
    const int warp = tid >> 5, lane = tid & 31;
    const int g = lane >> 2, tig = lane & 3;
    const int wm = warp >> 1, wn = warp & 1;
    const int rowBase = blockIdx.x * 128;

    float acc[2][NT][4];
#pragma unroll
    for (int mt = 0; mt < 2; mt++)
#pragma unroll
        for (int nt = 0; nt < NT; nt++)
#pragma unroll
            for (int i = 0; i < 4; i++) acc[mt][nt][i] = 0.f;

    const uint32_t* BpBlock = Bp + (size_t)blockIdx.y * nChunks * BN * 32;

    for (int c = 0; c < nChunks; c++) {
        const int k0 = c * 32;
        // ---- fill A (conflict-free STS.32; coalesced LDG) ----
#pragma unroll
        for (int i = 0; i < 16; i++) {
            int idx = tid + i * 256;            // 4096 elements
            int m = idx >> 5, k = idx & 31;
            int gk = k0 + k;
            float v = (gk < K) ? A[(size_t)(rowBase + m) * K + gk] * aScale : 0.f;
            int pos = ((k & 3) << 1) | ((k >> 2) & 1);
            As[m * 40 + (k >> 3) * 8 + pos] = f2tf32(v);
        }
        // ---- fill B (straight permuted copy, float4) ----
        {
            const uint4* src = (const uint4*)(BpBlock + (size_t)c * BN * 32);
#pragma unroll
            for (int i = 0; i < BN / 32; i++) {
                int idx = tid + i * 256;        // BN*8 16B-chunks
                int n = idx >> 3, o4 = (idx & 7) * 4;
                *(uint4*)&Bs[n * 40 + o4] = src[idx];
            }
        }
        __syncthreads();

#pragma unroll
        for (int kt = 0; kt < 4; kt++) {
            uint32_t a[2][4];
#pragma unroll
            for (int mt = 0; mt < 2; mt++) {
                const uint32_t* base = As + (wm * 32 + mt * 16 + g) * 40 + kt * 8 + 2 * tig;
                uint2 p0 = *(const uint2*)base;            // a0 (k=tig), a2 (k=tig+4)
                uint2 p1 = *(const uint2*)(base + 8 * 40); // rows +8: a1, a3
                a[mt][0] = p0.x; a[mt][1] = p1.x; a[mt][2] = p0.y; a[mt][3] = p1.y;
            }
#pragma unroll
            for (int nt = 0; nt < NT; nt++) {
                const uint32_t* bb = Bs + (wn * WN + nt * 8 + g) * 40 + kt * 8 + 2 * tig;
                uint2 q = *(const uint2*)bb;               // b0 (k=tig), b1 (k=tig+4)
#pragma unroll
                for (int mt = 0; mt < 2; mt++) {
                    asm volatile(
                        "mma.sync.aligned.m16n8k8.row.col.f32.tf32.tf32.f32 "
                        "{%0,%1,%2,%3}, {%4,%5,%6,%7}, {%8,%9}, {%0,%1,%2,%3};\n"
                        : "+f"(acc[mt][nt][0]), "+f"(acc[mt][nt][1]),
                          "+f"(acc[mt][nt][2]), "+f"(acc[mt][nt][3])
                        : "r"(a[mt][0]), "r"(a[mt][1]), "r"(a[mt][2]), "r"(a[mt][3]),
                          "r"(q.x), "r"(q.y));
                }
            }
        }
        __syncthreads();
    }

    // ---- epilogue: bias (+bias2), optional relu, float2 stores ----
    const int colBase = blockIdx.y * BN + wn * WN;
#pragma unroll
    for (int nt = 0; nt < NT; nt++) {
        int col = colBase + nt * 8 + 2 * tig;
        float bv0 = bias[col], bv1 = bias[col + 1];
        if (bias2) { bv0 += bias2[col]; bv1 += bias2[col + 1]; }
#pragma unroll
        for (int mt = 0; mt < 2; mt++) {
            int row = rowBase + wm * 32 + mt * 16 + g;
            float c0 = acc[mt][nt][0] + bv0;
            float c1 = acc[mt][nt][1] + bv1;
            float c2 = acc[mt][nt][2] + bv0;
            float c3 = acc[mt][nt][3] + bv1;
            if (RELU) {
                c0 = fmaxf(c0, 0.f); c1 = fmaxf(c1, 0.f);
                c2 = fmaxf(c2, 0.f); c3 = fmaxf(c3, 0.f);
            }
            *(float2*)&C[(size_t)row * ldc + coff + col] = make_float2(c0, c1);
            *(float2*)&C[(size_t)(row + 8) * ldc + coff + col] = make_float2(c2, c3);
        }
    }
}

// ---------------------------------------------------------------------------
// Tiny loc/energy encoders -> feats columns [32:64) and [64:96)
// ---------------------------------------------------------------------------
__global__ void smallenc_kernel(const float* __restrict__ loc,
                                const float* __restrict__ eng,
                                const float* __restrict__ Wl,
                                const float* __restrict__ bl,
                                const float* __restrict__ We,
                                const float* __restrict__ be,
                                float* __restrict__ feats)
{
    int idx = blockIdx.x * blockDim.x + threadIdx.x;
    if (idx >= N_TOT * 64) return;
    int n = idx >> 6;
    int j = idx & 63;
    if (j < 32) {
        float v = (loc[n * 2 + 0] * 0.1f) * Wl[j] +
                  (loc[n * 2 + 1] * 0.1f) * Wl[32 + j] + bl[j];
        feats[(size_t)n * 96 + 32 + j] = v;
    } else {
        int jj = j - 32;
        float v = (eng[n] * (1.f / 200.f)) * We[jj] + be[jj];
        feats[(size_t)n * 96 + 64 + jj] = v;
    }
}

// ---------------------------------------------------------------------------
// LSTM: one CTA owns LROWS batch rows, loops all T=128 steps locally.
// gates = gx (precomputed x@Wih^T + bih + bhh) + h @ Whh^T. Heads fused.
// ---------------------------------------------------------------------------
#define LROWS 16

__global__ __launch_bounds__(512) void lstm_kernel(
    const float* __restrict__ gx, const int* __restrict__ done,
    const float* __restrict__ h0, const float* __restrict__ c0,
    const float* __restrict__ Whh,
    const float* __restrict__ Wa, const float* __restrict__ ba,
    const float* __restrict__ Wc, const float* __restrict__ bc,
    float* __restrict__ out)
{
    __shared__ __align__(16) float h_s[LROWS][HID];   // 8 KB
    __shared__ __align__(16) float c_s[LROWS][HID];   // 8 KB
    __shared__ float gs[LROWS][4 * HID];              // 32 KB

    const int tid = threadIdx.x;      // 512 threads: one per gate column j
    const int r0 = blockIdx.x * LROWS;

    for (int e = tid; e < LROWS * HID; e += 512) {
        int r = e >> 7, k = e & 127;
        h_s[r][k] = h0[(r0 + r) * HID + k];
        c_s[r][k] = c0[(r0 + r) * HID + k];
    }
    __syncthreads();

    for (int t = 0; t < T_LEN; t++) {
        for (int e = tid; e < LROWS * HID; e += 512) {
            int r = e >> 7, k = e & 127;
            if (done[t * B_ENV + r0 + r]) { h_s[r][k] = 0.f; c_s[r][k] = 0.f; }
        }
        __syncthreads();

        {
            const int j = tid;
            float acc[LROWS];
            const float* gxp = gx + ((size_t)t * B_ENV + r0) * 512 + j;
#pragma unroll
            for (int r = 0; r < LROWS; r++) acc[r] = gxp[r * 512];

            const float4* wp = (const float4*)(Whh + j * HID);
#pragma unroll 8
            for (int kk = 0; kk < HID / 4; kk++) {
                float4 w = wp[kk];
#pragma unroll
                for (int r = 0; r < LROWS; r++) {
                    float4 h4 = *(const float4*)&h_s[r][kk * 4];
                    acc[r] += w.x * h4.x + w.y * h4.y + w.z * h4.z + w.w * h4.w;
                }
            }
#pragma unroll
            for (int r = 0; r < LROWS; r++) gs[r][j] = acc[r];
        }
        __syncthreads();

        for (int e = tid; e < LROWS * HID; e += 512) {
            int r = e >> 7, k = e & 127;
            float ig = gs[r][k];
            float fg = gs[r][HID + k];
            float gg = gs[r][2 * HID + k];
            float og = gs[r][3 * HID + k];
            float c = sigf(fg) * c_s[r][k] + sigf(ig) * tanhf(gg);
            c_s[r][k] = c;
            h_s[r][k] = sigf(og) * tanhf(c);
        }
        __syncthreads();

        if (tid < LROWS * (NA + 1)) {
            int r = tid / (NA + 1);
            int col = tid % (NA + 1);
            float s;
            if (col < NA) {
                s = ba[col];
                for (int k = 0; k < HID; k++) s += h_s[r][k] * Wa[k * NA + col];
            } else {
                s = bc[0];
                for (int k = 0; k < HID; k++) s += h_s[r][k] * Wc[k];
            }
            out[((size_t)t * B_ENV + r0 + r) * (NA + 1) + col] = s;
        }
        __syncthreads();
    }
}

// ---------------------------------------------------------------------------
// Launch
// ---------------------------------------------------------------------------
extern "C" void kernel_launch(void* const* d_in, const int* in_sizes, int n_in,
                              void* d_out, int out_size)
{
    const float* image = (const float*)d_in[0];
    const float* location = (const float*)d_in[1];
    const float* energy = (const float*)d_in[2];
    const int*   done  = (const int*)d_in[3];
    const float* h0 = (const float*)d_in[4];
    const float* c0 = (const float*)d_in[5];
    const float* W1 = (const float*)d_in[6];
    const float* b1 = (const float*)d_in[7];
    const float* W2 = (const float*)d_in[8];
    const float* b2 = (const float*)d_in[9];
    const float* W3 = (const float*)d_in[10];
    const float* b3 = (const float*)d_in[11];
    const float* W4 = (const float*)d_in[12];
    const float* b4 = (const float*)d_in[13];
    const float* Wl = (const float*)d_in[14];
    const float* bl = (const float*)d_in[15];
    const float* We = (const float*)d_in[16];
    const float* be = (const float*)d_in[17];
    const float* Wih = (const float*)d_in[18];
    const float* Whh = (const float*)d_in[19];
    const float* bih = (const float*)d_in[20];
    const float* bhh = (const float*)d_in[21];
    const float* Wa = (const float*)d_in[22];
    const float* ba = (const float*)d_in[23];
    const float* Wc = (const float*)d_in[24];
    const float* bc = (const float*)d_in[25];
    float* out = (float*)d_out;

    float *pb0, *pb1, *pfeat, *pgx;
    uint32_t* pbp;
    cudaGetSymbolAddress((void**)&pb0, g_b0);
    cudaGetSymbolAddress((void**)&pb1, g_b1);
    cudaGetSymbolAddress((void**)&pfeat, g_feat);
    cudaGetSymbolAddress((void**)&pgx, g_gx);
    cudaGetSymbolAddress((void**)&pbp, g_bperm);

    // Permuted-B buffer offsets (words = N*32*nChunks)
    //   L1: N=256 K=25  nC=1 -> 8192
    //   L2: N=256 K=256 nC=8 -> 65536
    //   L3: N=128 K=256 nC=8 -> 32768
    //   L4: N=32  K=128 nC=4 -> 4096
    //   gx: N=512 K=96  nC=3 -> 49152
    uint32_t* bp1 = pbp;
    uint32_t* bp2 = bp1 + 8192;
    uint32_t* bp3 = bp2 + 65536;
    uint32_t* bp4 = bp3 + 32768;
    uint32_t* bpg = bp4 + 4096;

    bperm_kernel<false><<<(8192 + 255) / 256, 256>>>(W1, bp1, 256, 25, 128, 1);
    bperm_kernel<false><<<(65536 + 255) / 256, 256>>>(W2, bp2, 256, 256, 128, 8);
    bperm_kernel<false><<<(32768 + 255) / 256, 256>>>(W3, bp3, 128, 256, 128, 8);
    bperm_kernel<false><<<(4096 + 255) / 256, 256>>>(W4, bp4, 32, 128, 32, 4);
    bperm_kernel<true><<<(49152 + 255) / 256, 256>>>(Wih, bpg, 512, 96, 128, 3);

    const int MB = N_TOT / 128;   // 4096 row blocks

    // L1: [N,25] @ W1 -> relu -> b0 (ldc=256)
    gemm_tf32<128, true><<<dim3(MB, 2), 256>>>(image, bp1, b1, nullptr, pb0, 25, 1, 1.f / 255.f, 256, 0);
    // L2: [N,256] @ W2 -> relu -> b1
    gemm_tf32<128, true><<<dim3(MB, 2), 256>>>(pb0, bp2, b2, nullptr, pb1, 256, 8, 1.f, 256, 0);
    // L3: [N,256] @ W3 -> relu -> b0 (ldc=128)
    gemm_tf32<128, true><<<dim3(MB, 1), 256>>>(pb1, bp3, b3, nullptr, pb0, 256, 8, 1.f, 128, 0);
    // L4: [N,128] @ W4 -> relu -> feats[:,0:32] (ldc=96)
    gemm_tf32<32, true><<<dim3(MB, 1), 256>>>(pb0, bp4, b4, nullptr, pfeat, 128, 4, 1.f, 96, 0);
    // loc / energy encoders -> feats[:, 32:96]
    smallenc_kernel<<<(N_TOT * 64 + 255) / 256, 256>>>(location, energy, Wl, bl, We, be, pfeat);
    // gx: [N,96] @ Wih^T + bih + bhh (ldc=512)
    gemm_tf32<128, false><<<dim3(MB, 4), 256>>>(pfeat, bpg, bih, bhh, pgx, 96, 3, 1.f, 512, 0);
    // LSTM recurrence + fused heads
    lstm_kernel<<<B_ENV / LROWS, 512>>>(pgx, done, h0, c0, Whh, Wa, ba, Wc, bc, out);
}

// round 5
// speedup vs baseline: 1.6829x; 1.6829x over previous
#include <cuda_runtime.h>
#include <math.h>
#include <stdint.h>

// Problem constants (fixed by the reference)
#define T_LEN 128
#define B_ENV 4096
#define N_TOT (T_LEN * B_ENV)   // 524288
#define HID   128
#define NA    6

// ---------------------------------------------------------------------------
// Scratch (device globals — no runtime allocation allowed)
// ---------------------------------------------------------------------------
__device__ float g_b0[(size_t)N_TOT * 256];   // 512 MB ping
__device__ float g_b1[(size_t)N_TOT * 256];   // 512 MB pong
__device__ float g_act[(size_t)N_TOT * 36];   // 75 MB  [img_feat(32)|loc(2)|eng(1)|0]
__device__ float g_gx[(size_t)N_TOT * 512];   // 1 GB   precomputed x-gates
__device__ float g_wt[262144];                // transposed / combined weights
__device__ float g_bg[512];                   // combined gate bias

__device__ __forceinline__ float sigf(float x) { return 1.f / (1.f + expf(-x)); }

// ---------------------------------------------------------------------------
// Packed f32x2 helpers (Blackwell base-family ISA)
// ---------------------------------------------------------------------------
typedef unsigned long long u64;
__device__ __forceinline__ u64 pack2(float lo, float hi) {
    u64 r; asm("mov.b64 %0, {%1, %2};" : "=l"(r) : "f"(lo), "f"(hi)); return r;
}
__device__ __forceinline__ u64 dup2(float x) {
    u64 r; asm("mov.b64 %0, {%1, %1};" : "=l"(r) : "f"(x)); return r;
}
__device__ __forceinline__ void fma2(u64& acc, u64 a, u64 b) {
    asm("fma.rn.f32x2 %0, %1, %2, %0;" : "+l"(acc) : "l"(a), "l"(b));
}
__device__ __forceinline__ void unpack2(u64 v, float& lo, float& hi) {
    asm("mov.b64 {%0, %1}, %2;" : "=f"(lo), "=f"(hi) : "l"(v));
}

// ---------------------------------------------------------------------------
// Weight prep
// ---------------------------------------------------------------------------
// Transpose [K,N] -> [N,Kpad] (K-major rows, zero-padded)
__global__ void prep_wT(const float* __restrict__ W, float* __restrict__ out,
                        int K, int N, int Kpad)
{
    int idx = blockIdx.x * 256 + threadIdx.x;
    if (idx >= N * Kpad) return;
    int n = idx / Kpad, k = idx % Kpad;
    out[idx] = (k < K) ? W[(size_t)k * N + n] : 0.f;
}

// Combined gx weight Wg[512][48]:
//   k<32 : Wih[n, k]                      (image-feature part)
//   k=32,33: (1/GRID) * sum_j Wl[d,j] * Wih[n, 32+j]   (d = k-32)
//   k=34 : (1/MAXE) * sum_j We[0,j] * Wih[n, 64+j]
//   else : 0
__global__ void prep_wg(const float* __restrict__ Wih, const float* __restrict__ Wl,
                        const float* __restrict__ We, float* __restrict__ out)
{
    int idx = blockIdx.x * 256 + threadIdx.x;
    if (idx >= 512 * 48) return;
    int n = idx / 48, k = idx % 48;
    float v = 0.f;
    if (k < 32) {
        v = Wih[n * 96 + k];
    } else if (k < 34) {
        int d = k - 32;
        float s = 0.f;
        for (int j = 0; j < 32; j++) s += Wl[d * 32 + j] * Wih[n * 96 + 32 + j];
        v = s * 0.1f;
    } else if (k == 34) {
        float s = 0.f;
        for (int j = 0; j < 32; j++) s += We[j] * Wih[n * 96 + 64 + j];
        v = s * (1.f / 200.f);
    }
    out[idx] = v;
}

// Combined bias: bih + bhh + bl@Wih[:,32:64]^T + be@Wih[:,64:96]^T
__global__ void prep_bg(const float* __restrict__ Wih, const float* __restrict__ bl,
                        const float* __restrict__ be, const float* __restrict__ bih,
                        const float* __restrict__ bhh, float* __restrict__ bg)
{
    int n = blockIdx.x * 256 + threadIdx.x;
    if (n >= 512) return;
    float s = bih[n] + bhh[n];
    for (int j = 0; j < 32; j++)
        s += bl[j] * Wih[n * 96 + 32 + j] + be[j] * Wih[n * 96 + 64 + j];
    bg[n] = s;
}

// act[:,32..35] = {loc0, loc1, eng, 0} (raw; scales folded into Wg)
__global__ void act_fill(const float* __restrict__ loc, const float* __restrict__ eng,
                         float* __restrict__ act)
{
    int n = blockIdx.x * 256 + threadIdx.x;
    if (n >= N_TOT) return;
    float4 v;
    v.x = loc[2 * n]; v.y = loc[2 * n + 1]; v.z = eng[n]; v.w = 0.f;
    *(float4*)&act[(size_t)n * 36 + 32] = v;
}

// ---------------------------------------------------------------------------
// f32x2 SGEMM: C[M,N] = act(A[M,K]*aScale @ Bt^T + bias)
//   A: [M, lda] row-major.  Bt: [N, Kpad] row-major (pre-transposed, padded).
//   Tile 128 x BN, BK=16, 256 threads; per-thread 8(m) x TN(n), m packed in pairs.
// ---------------------------------------------------------------------------
template <int BN, bool RELU>
__global__ __launch_bounds__(256) void gemm_f32x2(
    const float* __restrict__ A, const float* __restrict__ Bt,
    const float* __restrict__ bias, float* __restrict__ C,
    int K, int lda, int Kpad, float aScale, int ldc)
{
    constexpr int TN = BN / 16;
    __shared__ __align__(16) float As[16][132];
    __shared__ __align__(16) float Bs[16][BN + 4];

    const int tid = threadIdx.x;
    const int tr = tid >> 4, tc = tid & 15;
    const int rowBase = blockIdx.x * 128;
    const int colBase = blockIdx.y * BN;
    const float* BtB = Bt + (size_t)colBase * Kpad;

    u64 acc[4][TN];
#pragma unroll
    for (int ip = 0; ip < 4; ip++)
#pragma unroll
        for (int j = 0; j < TN; j++) acc[ip][j] = 0ull;

    const int nC = Kpad / 16;
    for (int c = 0; c < nC; c++) {
        const int k0 = c * 16;
        // ---- A tile: 128 x 16 ----
#pragma unroll
        for (int i = 0; i < 8; i++) {
            int idx = tid + i * 256;
            int m = idx >> 4, k = idx & 15;
            int gk = k0 + k;
            As[k][m] = (gk < K) ? A[(size_t)(rowBase + m) * lda + gk] * aScale : 0.f;
        }
        // ---- B tile: BN x 16 (pre-padded, no guard) ----
#pragma unroll
        for (int idx = tid; idx < 16 * BN; idx += 256) {
            int n = idx >> 4, k = idx & 15;
            Bs[k][n] = BtB[(size_t)n * Kpad + k0 + k];
        }
        __syncthreads();

#pragma unroll
        for (int k = 0; k < 16; k++) {
            ulonglong2 a01 = *(const ulonglong2*)&As[k][tr * 8];
            ulonglong2 a23 = *(const ulonglong2*)&As[k][tr * 8 + 4];
            u64 av[4] = {a01.x, a01.y, a23.x, a23.y};
            float bv[TN];
            if (TN == 8) {
                float4 b0 = *(const float4*)&Bs[k][tc * 8];
                float4 b1 = *(const float4*)&Bs[k][tc * 8 + 4];
                bv[0] = b0.x; bv[1] = b0.y; bv[2] = b0.z; bv[3] = b0.w;
                bv[4] = b1.x; bv[5] = b1.y; bv[6] = b1.z; bv[7] = b1.w;
            } else {
                float2 b0 = *(const float2*)&Bs[k][tc * TN];
                bv[0] = b0.x; bv[1] = b0.y;
            }
#pragma unroll
            for (int j = 0; j < TN; j++) {
                u64 bd = dup2(bv[j]);
#pragma unroll
                for (int ip = 0; ip < 4; ip++) fma2(acc[ip][j], av[ip], bd);
            }
        }
        __syncthreads();
    }

    // ---- epilogue ----
    const int col0 = colBase + tc * TN;
#pragma unroll
    for (int ip = 0; ip < 4; ip++) {
        const int r0 = rowBase + tr * 8 + 2 * ip;
        float o0[TN], o1[TN];
#pragma unroll
        for (int j = 0; j < TN; j++) {
            unpack2(acc[ip][j], o0[j], o1[j]);
            float bv = bias[col0 + j];
            o0[j] += bv; o1[j] += bv;
            if (RELU) { o0[j] = fmaxf(o0[j], 0.f); o1[j] = fmaxf(o1[j], 0.f); }
        }
        float* d0 = C + (size_t)r0 * ldc + col0;
        float* d1 = C + (size_t)(r0 + 1) * ldc + col0;
        if (TN == 8) {
            *(float4*)(d0) = make_float4(o0[0], o0[1], o0[2], o0[3]);
            *(float4*)(d0 + 4) = make_float4(o0[4], o0[5], o0[6], o0[7]);
            *(float4*)(d1) = make_float4(o1[0], o1[1], o1[2], o1[3]);
            *(float4*)(d1 + 4) = make_float4(o1[4], o1[5], o1[6], o1[7]);
        } else {
            *(float2*)(d0) = make_float2(o0[0], o0[1]);
            *(float2*)(d1) = make_float2(o1[0], o1[1]);
        }
    }
}

// ---------------------------------------------------------------------------
// LSTM: one CTA owns 16 batch rows, loops all T=128 steps locally.
// h stored transposed h_s[k][r] (row-pairs pack into f32x2); c in registers
// (fixed (k,r)->thread ownership). Gates use packed fma.f32x2. Heads fused.
// ---------------------------------------------------------------------------
#define LROWS 16

__global__ __launch_bounds__(512) void lstm_f32x2(
    const float* __restrict__ gx, const int* __restrict__ done,
    const float* __restrict__ h0, const float* __restrict__ c0,
    const float* __restrict__ Whh,
    const float* __restrict__ Wa, const float* __restrict__ ba,
    const float* __restrict__ Wc, const float* __restrict__ bc,
    float* __restrict__ out)
{
    __shared__ __align__(16) float h_s[HID][LROWS];   // 8 KB, transposed
    __shared__ float gs[4 * HID][17];                 // 34 KB, gate-major, padded

    const int tid = threadIdx.x;
    const int r0 = blockIdx.x * LROWS;

    float creg[4];
#pragma unroll
    for (int i = 0; i < 4; i++) {
        int e = tid + i * 512;
        int k = e >> 4, r = e & 15;
        h_s[k][r] = h0[(r0 + r) * HID + k];
        creg[i] = c0[(r0 + r) * HID + k];
    }
    __syncthreads();

    for (int t = 0; t < T_LEN; t++) {
        // ---- done mask ----
#pragma unroll
        for (int i = 0; i < 4; i++) {
            int e = tid + i * 512;
            int k = e >> 4, r = e & 15;
            if (done[t * B_ENV + r0 + r]) { h_s[k][r] = 0.f; creg[i] = 0.f; }
        }
        __syncthreads();

        // ---- gates: thread j = tid computes gates[*, j] for all 16 rows ----
        {
            const float* gp = gx + ((size_t)t * B_ENV + r0) * 512 + tid;
            u64 acc[8];
#pragma unroll
            for (int p = 0; p < 8; p++)
                acc[p] = pack2(gp[(size_t)(2 * p) * 512], gp[(size_t)(2 * p + 1) * 512]);

            const float4* w4 = (const float4*)(Whh + (size_t)tid * HID);
#pragma unroll 8
            for (int kk = 0; kk < 32; kk++) {
                float4 w = w4[kk];
                const float wv[4] = {w.x, w.y, w.z, w.w};
#pragma unroll
                for (int s = 0; s < 4; s++) {
                    int k = kk * 4 + s;
                    u64 wd = dup2(wv[s]);
                    const ulonglong2* hp = (const ulonglong2*)&h_s[k][0];
                    ulonglong2 hA = hp[0], hB = hp[1], hC = hp[2], hD = hp[3];
                    fma2(acc[0], wd, hA.x); fma2(acc[1], wd, hA.y);
                    fma2(acc[2], wd, hB.x); fma2(acc[3], wd, hB.y);
                    fma2(acc[4], wd, hC.x); fma2(acc[5], wd, hC.y);
                    fma2(acc[6], wd, hD.x); fma2(acc[7], wd, hD.y);
                }
            }
#pragma unroll
            for (int p = 0; p < 8; p++) {
                float lo, hi;
                unpack2(acc[p], lo, hi);
                gs[tid][2 * p] = lo;
                gs[tid][2 * p + 1] = hi;
            }
        }
        __syncthreads();

        // ---- elementwise LSTM update ----
#pragma unroll
        for (int i = 0; i < 4; i++) {
            int e = tid + i * 512;
            int k = e >> 4, r = e & 15;
            float ig = gs[k][r];
            float fg = gs[HID + k][r];
            float gg = gs[2 * HID + k][r];
            float og = gs[3 * HID + k][r];
            float c = sigf(fg) * creg[i] + sigf(ig) * tanhf(gg);
            creg[i] = c;
            h_s[k][r] = sigf(og) * tanhf(c);
        }
        __syncthreads();

        // ---- fused heads: logits (6) + value (1) ----
        if (tid < LROWS * (NA + 1)) {
            int r = tid / (NA + 1);
            int col = tid % (NA + 1);
            float s = (col < NA) ? ba[col] : bc[0];
            if (col < NA) {
#pragma unroll 8
                for (int k = 0; k < HID; k++) s += h_s[k][r] * Wa[k * NA + col];
            } else {
#pragma unroll 8
                for (int k = 0; k < HID; k++) s += h_s[k][r] * Wc[k];
            }
            out[((size_t)t * B_ENV + r0 + r) * (NA + 1) + col] = s;
        }
        __syncthreads();
    }
}

// ---------------------------------------------------------------------------
// Launch
// ---------------------------------------------------------------------------
extern "C" void kernel_launch(void* const* d_in, const int* in_sizes, int n_in,
                              void* d_out, int out_size)
{
    const float* image = (const float*)d_in[0];
    const float* location = (const float*)d_in[1];
    const float* energy = (const float*)d_in[2];
    const int*   done  = (const int*)d_in[3];
    const float* h0 = (const float*)d_in[4];
    const float* c0 = (const float*)d_in[5];
    const float* W1 = (const float*)d_in[6];
    const float* b1 = (const float*)d_in[7];
    const float* W2 = (const float*)d_in[8];
    const float* b2 = (const float*)d_in[9];
    const float* W3 = (const float*)d_in[10];
    const float* b3 = (const float*)d_in[11];
    const float* W4 = (const float*)d_in[12];
    const float* b4 = (const float*)d_in[13];
    const float* Wl = (const float*)d_in[14];
    const float* bl = (const float*)d_in[15];
    const float* We = (const float*)d_in[16];
    const float* be = (const float*)d_in[17];
    const float* Wih = (const float*)d_in[18];
    const float* Whh = (const float*)d_in[19];
    const float* bih = (const float*)d_in[20];
    const float* bhh = (const float*)d_in[21];
    const float* Wa = (const float*)d_in[22];
    const float* ba = (const float*)d_in[23];
    const float* Wc = (const float*)d_in[24];
    const float* bc = (const float*)d_in[25];
    float* out = (float*)d_out;

    float *pb0, *pb1, *pact, *pgx, *pwt, *pbg;
    cudaGetSymbolAddress((void**)&pb0, g_b0);
    cudaGetSymbolAddress((void**)&pb1, g_b1);
    cudaGetSymbolAddress((void**)&pact, g_act);
    cudaGetSymbolAddress((void**)&pgx, g_gx);
    cudaGetSymbolAddress((void**)&pwt, g_wt);
    cudaGetSymbolAddress((void**)&pbg, g_bg);

    // Weight scratch layout (floats): [N, Kpad]
    float* wt1 = pwt;               // 256 x 32  = 8192
    float* wt2 = wt1 + 8192;        // 256 x 256 = 65536
    float* wt3 = wt2 + 65536;       // 128 x 256 = 32768
    float* wt4 = wt3 + 32768;       // 32  x 128 = 4096
    float* wg  = wt4 + 4096;        // 512 x 48  = 24576

    prep_wT<<<(256 * 32 + 255) / 256, 256>>>(W1, wt1, 25, 256, 32);
    prep_wT<<<(256 * 256 + 255) / 256, 256>>>(W2, wt2, 256, 256, 256);
    prep_wT<<<(128 * 256 + 255) / 256, 256>>>(W3, wt3, 256, 128, 256);
    prep_wT<<<(32 * 128 + 255) / 256, 256>>>(W4, wt4, 128, 32, 128);
    prep_wg<<<(512 * 48 + 255) / 256, 256>>>(Wih, Wl, We, wg);
    prep_bg<<<2, 256>>>(Wih, bl, be, bih, bhh, pbg);
    act_fill<<<(N_TOT + 255) / 256, 256>>>(location, energy, pact);

    const int MB = N_TOT / 128;   // 4096 row tiles

    // L1: [N,25] @ W1 -> relu -> b0 (ldc=256)
    gemm_f32x2<128, true><<<dim3(MB, 2), 256>>>(image, wt1, b1, pb0, 25, 25, 32, 1.f / 255.f, 256);
    // L2: [N,256] @ W2 -> relu -> b1
    gemm_f32x2<128, true><<<dim3(MB, 2), 256>>>(pb0, wt2, b2, pb1, 256, 256, 256, 1.f, 256);
    // L3: [N,256] @ W3 -> relu -> b0 (ldc=128)
    gemm_f32x2<128, true><<<dim3(MB, 1), 256>>>(pb1, wt3, b3, pb0, 256, 256, 256, 1.f, 128);
    // L4: [N,128] @ W4 -> relu -> act[:,0:32] (ldc=36)
    gemm_f32x2<32, true><<<dim3(MB, 1), 256>>>(pb0, wt4, b4, pact, 128, 128, 128, 1.f, 36);
    // gx: [N,36] @ Wg^T + bg (ldc=512) — loc/energy encoders folded into Wg
    gemm_f32x2<128, false><<<dim3(MB, 4), 256>>>(pact, wg, pbg, pgx, 36, 36, 48, 1.f, 512);
    // LSTM recurrence + fused heads
    lstm_f32x2<<<B_ENV / LROWS, 512>>>(pgx, done, h0, c0, Whh, Wa, ba, Wc, bc, out);
}

// round 6
// speedup vs baseline: 1.7168x; 1.0201x over previous
#include <cuda_runtime.h>
#include <math.h>
#include <stdint.h>

// Problem constants (fixed by the reference)
#define T_LEN 128
#define B_ENV 4096
#define N_TOT (T_LEN * B_ENV)   // 524288
#define HID   128
#define NA    6

// ---------------------------------------------------------------------------
// Scratch (device globals — no runtime allocation allowed)
// ---------------------------------------------------------------------------
__device__ float g_f2[(size_t)N_TOT * 256];   // 512 MB  (f2 activations)
__device__ float g_gx[(size_t)N_TOT * 512];   // 1 GB    (precomputed x-gates)
__device__ float g_wg[36 * 512];              // combined gx weight, k-major
__device__ float g_bg[512];                   // combined gate bias

__device__ __forceinline__ float sigf(float x) { return 1.f / (1.f + expf(-x)); }

// ---------------------------------------------------------------------------
// Packed f32x2 helpers
// ---------------------------------------------------------------------------
typedef unsigned long long u64;
__device__ __forceinline__ u64 pack2(float lo, float hi) {
    u64 r; asm("mov.b64 %0, {%1, %2};" : "=l"(r) : "f"(lo), "f"(hi)); return r;
}
__device__ __forceinline__ u64 dup2(float x) {
    u64 r; asm("mov.b64 %0, {%1, %1};" : "=l"(r) : "f"(x)); return r;
}
__device__ __forceinline__ void fma2(u64& acc, u64 a, u64 b) {
    asm("fma.rn.f32x2 %0, %1, %2, %0;" : "+l"(acc) : "l"(a), "l"(b));
}
__device__ __forceinline__ void unpack2(u64 v, float& lo, float& hi) {
    asm("mov.b64 {%0, %1}, %2;" : "=f"(lo), "=f"(hi) : "l"(v));
}

// ---------------------------------------------------------------------------
// Weight prep: combined gx weight (k-major [36][512]) and bias.
// gates_x = img_feat@Wih[:, :32]^T + (loc/10)@Wl@Wih[:,32:64]^T
//         + (eng/200)@We@Wih[:,64:96]^T + (bl@..., be@..., bih, bhh folded)
// ---------------------------------------------------------------------------
__global__ void prep_wg(const float* __restrict__ Wih, const float* __restrict__ Wl,
                        const float* __restrict__ We, float* __restrict__ out)
{
    int idx = blockIdx.x * 256 + threadIdx.x;
    if (idx >= 36 * 512) return;
    int k = idx >> 9, n = idx & 511;
    float v = 0.f;
    if (k < 32) {
        v = Wih[n * 96 + k];
    } else if (k < 34) {
        int d = k - 32;
        float s = 0.f;
        for (int j = 0; j < 32; j++) s += Wl[d * 32 + j] * Wih[n * 96 + 32 + j];
        v = s * 0.1f;
    } else if (k == 34) {
        float s = 0.f;
        for (int j = 0; j < 32; j++) s += We[j] * Wih[n * 96 + 64 + j];
        v = s * (1.f / 200.f);
    }
    out[k * 512 + n] = v;
}

__global__ void prep_bg(const float* __restrict__ Wih, const float* __restrict__ bl,
                        const float* __restrict__ be, const float* __restrict__ bih,
                        const float* __restrict__ bhh, float* __restrict__ bg)
{
    int n = blockIdx.x * 256 + threadIdx.x;
    if (n >= 512) return;
    float s = bih[n] + bhh[n];
    for (int j = 0; j < 32; j++)
        s += bl[j] * Wih[n * 96 + 32 + j] + be[j] * Wih[n * 96 + 64 + j];
    bg[n] = s;
}

// ---------------------------------------------------------------------------
// Fused L1+L2: image[128rows,25] -> f1(SMEM, k-major) -> f2 (global, relu)
// 512 threads, tile 128 x 256, per-thread 8 rows (4 pairs) x 8 cols.
// ---------------------------------------------------------------------------
#define S1 130   // k-major row stride (even, !=0 mod 4 would break align; 130 ok)

__global__ __launch_bounds__(512) void fused12(
    const float* __restrict__ img, const float* __restrict__ W1,
    const float* __restrict__ b1, const float* __restrict__ W2,
    const float* __restrict__ b2, float* __restrict__ f2)
{
    extern __shared__ float sm[];
    float* f1k = sm;                     // [256][S1]  k-major f1
    float* xsk = f1k + 256 * S1;         // [26][S1]   k-major scaled image
    float* bs  = xsk + 26 * S1;          // [32][264]  B staging (2 x 16 rows)

    const int tid = threadIdx.x;
    const int wr = tid >> 5;             // 0..15 : row group (rows wr*8..+7)
    const int tc = tid & 31;             // 0..31 : col group (cols tc*8..+7)
    const int rowBase = blockIdx.x * 128;

    // ---- stage image tile, k-major, scaled ----
    for (int i = tid; i < 128 * 25; i += 512) {
        int k = i % 25, m = i / 25;
        xsk[k * S1 + m] = img[(size_t)(rowBase + m) * 25 + k] * (1.f / 255.f);
    }
    // ---- stage W1 (natural k-major [25][256]) ----
    for (int i = tid; i < 25 * 256; i += 512) {
        int k = i >> 8, n = i & 255;
        bs[k * 264 + n] = W1[i];
    }
    __syncthreads();

    // ================= phase 1: f1 = relu(x @ W1 + b1), K=25 =================
    {
        u64 acc[4][8];
#pragma unroll
        for (int p = 0; p < 4; p++)
#pragma unroll
            for (int j = 0; j < 8; j++) acc[p][j] = 0ull;

        for (int k = 0; k < 25; k++) {
            const float* ar = xsk + k * S1 + wr * 8;
            u64 a0 = *(const u64*)(ar);
            u64 a1 = *(const u64*)(ar + 2);
            u64 a2 = *(const u64*)(ar + 4);
            u64 a3 = *(const u64*)(ar + 6);
            float4 q0 = *(const float4*)(bs + k * 264 + tc * 8);
            float4 q1 = *(const float4*)(bs + k * 264 + tc * 8 + 4);
            float bv[8] = {q0.x, q0.y, q0.z, q0.w, q1.x, q1.y, q1.z, q1.w};
#pragma unroll
            for (int j = 0; j < 8; j++) {
                u64 bd = dup2(bv[j]);
                fma2(acc[0][j], a0, bd); fma2(acc[1][j], a1, bd);
                fma2(acc[2][j], a2, bd); fma2(acc[3][j], a3, bd);
            }
        }
        // bias + relu, write f1 K-MAJOR into SMEM
        float4 c0 = *(const float4*)(b1 + tc * 8);
        float4 c1 = *(const float4*)(b1 + tc * 8 + 4);
        float bias0[8] = {c0.x, c0.y, c0.z, c0.w, c1.x, c1.y, c1.z, c1.w};
#pragma unroll
        for (int p = 0; p < 4; p++) {
            int m0 = wr * 8 + 2 * p;
#pragma unroll
            for (int j = 0; j < 8; j++) {
                float o0, o1;
                unpack2(acc[p][j], o0, o1);
                o0 = fmaxf(o0 + bias0[j], 0.f);
                o1 = fmaxf(o1 + bias0[j], 0.f);
                *(u64*)&f1k[(tc * 8 + j) * S1 + m0] = pack2(o0, o1);
            }
        }
    }
    __syncthreads();

    // ================= phase 2: f2 = relu(f1 @ W2 + b2), K=256 ================
    u64 acc[4][8];
#pragma unroll
    for (int p = 0; p < 4; p++)
#pragma unroll
        for (int j = 0; j < 8; j++) acc[p][j] = 0ull;

    float ldr[8];
#define LOADW2(c)                                                      \
    _Pragma("unroll") for (int i = 0; i < 8; i++) {                    \
        int idx = tid + i * 512;                                       \
        int k = idx >> 8, n = idx & 255;                               \
        ldr[i] = W2[(size_t)((c) * 16 + k) * 256 + n];                 \
    }
#define STW2(buf)                                                      \
    _Pragma("unroll") for (int i = 0; i < 8; i++) {                    \
        int idx = tid + i * 512;                                       \
        int k = idx >> 8, n = idx & 255;                               \
        bs[((buf) * 16 + k) * 264 + n] = ldr[i];                       \
    }

    LOADW2(0); STW2(0); __syncthreads();
    for (int c = 0; c < 16; c++) {
        if (c < 15) { LOADW2(c + 1); }
        const float* bsc = bs + (c & 1) * 16 * 264;
        const float* f1c = f1k + c * 16 * S1;
#pragma unroll
        for (int k = 0; k < 16; k++) {
            const float* ar = f1c + k * S1 + wr * 8;
            u64 a0 = *(const u64*)(ar);
            u64 a1 = *(const u64*)(ar + 2);
            u64 a2 = *(const u64*)(ar + 4);
            u64 a3 = *(const u64*)(ar + 6);
            float4 q0 = *(const float4*)(bsc + k * 264 + tc * 8);
            float4 q1 = *(const float4*)(bsc + k * 264 + tc * 8 + 4);
            float bv[8] = {q0.x, q0.y, q0.z, q0.w, q1.x, q1.y, q1.z, q1.w};
#pragma unroll
            for (int j = 0; j < 8; j++) {
                u64 bd = dup2(bv[j]);
                fma2(acc[0][j], a0, bd); fma2(acc[1][j], a1, bd);
                fma2(acc[2][j], a2, bd); fma2(acc[3][j], a3, bd);
            }
        }
        __syncthreads();
        if (c < 15) { STW2((c + 1) & 1); }
        __syncthreads();
    }

    // epilogue: bias + relu -> global f2 (row-major), float4 stores
    {
        float4 c0 = *(const float4*)(b2 + tc * 8);
        float4 c1 = *(const float4*)(b2 + tc * 8 + 4);
        float bias0[8] = {c0.x, c0.y, c0.z, c0.w, c1.x, c1.y, c1.z, c1.w};
#pragma unroll
        for (int p = 0; p < 4; p++) {
            int m0 = rowBase + wr * 8 + 2 * p;
            float o0[8], o1[8];
#pragma unroll
            for (int j = 0; j < 8; j++) {
                unpack2(acc[p][j], o0[j], o1[j]);
                o0[j] = fmaxf(o0[j] + bias0[j], 0.f);
                o1[j] = fmaxf(o1[j] + bias0[j], 0.f);
            }
            float* d0 = f2 + (size_t)m0 * 256 + tc * 8;
            float* d1 = f2 + (size_t)(m0 + 1) * 256 + tc * 8;
            *(float4*)(d0)     = make_float4(o0[0], o0[1], o0[2], o0[3]);
            *(float4*)(d0 + 4) = make_float4(o0[4], o0[5], o0[6], o0[7]);
            *(float4*)(d1)     = make_float4(o1[0], o1[1], o1[2], o1[3]);
            *(float4*)(d1 + 4) = make_float4(o1[4], o1[5], o1[6], o1[7]);
        }
    }
#undef LOADW2
#undef STW2
}

// ---------------------------------------------------------------------------
// Fused L3+L4+loc/eng+gx: f2[128rows,256] -> f3 -> f4(+loc/eng) -> gx
// 512 threads.
// ---------------------------------------------------------------------------
#define S3 130

__global__ __launch_bounds__(512) void fused345(
    const float* __restrict__ f2, const float* __restrict__ loc,
    const float* __restrict__ eng,
    const float* __restrict__ W3, const float* __restrict__ b3,
    const float* __restrict__ W4, const float* __restrict__ b4,
    const float* __restrict__ wg, const float* __restrict__ bg,
    float* __restrict__ gx)
{
    extern __shared__ float sm[];
    float* f3k = sm;                      // [128][S3]
    float* f4k = f3k + 128 * S3;          // [36][S3]
    float* as2 = f4k + 36 * S3;           // 2 x [16][S3]
    float* bs3 = as2 + 32 * S3;           // 2 x [16][132]
    float* bsg = bs3 + 32 * 132;          // [36][516]

    const int tid = threadIdx.x;
    const int wr = tid >> 5;              // 16 groups x 8 rows
    const int tc = tid & 31;
    const int rowBase = blockIdx.x * 128;

    // ---- stage full Wg (k-major [36][512]) ----
    for (int i = tid; i < 36 * 512; i += 512) {
        int k = i >> 9, n = i & 511;
        bsg[k * 516 + n] = wg[i];
    }

    // ================= phase L3: f3 = relu(f2 @ W3 + b3), K=256 ===============
    {
        u64 acc[4][4];
#pragma unroll
        for (int p = 0; p < 4; p++)
#pragma unroll
            for (int j = 0; j < 4; j++) acc[p][j] = 0ull;

        float lA[4], lB[4];
#define LD3(c)                                                         \
    _Pragma("unroll") for (int i = 0; i < 4; i++) {                    \
        int idx = tid + i * 512;                                       \
        int ka = idx & 15, ma = idx >> 4;                              \
        lA[i] = f2[(size_t)(rowBase + ma) * 256 + (c) * 16 + ka];      \
        int nb = idx & 127, kb = idx >> 7;                             \
        lB[i] = W3[(size_t)((c) * 16 + kb) * 128 + nb];                \
    }
#define ST3(buf)                                                       \
    _Pragma("unroll") for (int i = 0; i < 4; i++) {                    \
        int idx = tid + i * 512;                                       \
        int ka = idx & 15, ma = idx >> 4;                              \
        as2[((buf) * 16 + ka) * S3 + ma] = lA[i];                      \
        int nb = idx & 127, kb = idx >> 7;                             \
        bs3[((buf) * 16 + kb) * 132 + nb] = lB[i];                     \
    }
        LD3(0); ST3(0); __syncthreads();
        for (int c = 0; c < 16; c++) {
            if (c < 15) { LD3(c + 1); }
            const float* ab = as2 + (c & 1) * 16 * S3;
            const float* bb = bs3 + (c & 1) * 16 * 132;
#pragma unroll
            for (int k = 0; k < 16; k++) {
                const float* ar = ab + k * S3 + wr * 8;
                u64 a0 = *(const u64*)(ar);
                u64 a1 = *(const u64*)(ar + 2);
                u64 a2 = *(const u64*)(ar + 4);
                u64 a3 = *(const u64*)(ar + 6);
                float4 q = *(const float4*)(bb + k * 132 + tc * 4);
                float bv[4] = {q.x, q.y, q.z, q.w};
#pragma unroll
                for (int j = 0; j < 4; j++) {
                    u64 bd = dup2(bv[j]);
                    fma2(acc[0][j], a0, bd); fma2(acc[1][j], a1, bd);
                    fma2(acc[2][j], a2, bd); fma2(acc[3][j], a3, bd);
                }
            }
            __syncthreads();
            if (c < 15) { ST3((c + 1) & 1); }
            __syncthreads();
        }
        // bias + relu -> f3 k-major in SMEM
        float4 cb = *(const float4*)(b3 + tc * 4);
        float bias0[4] = {cb.x, cb.y, cb.z, cb.w};
#pragma unroll
        for (int p = 0; p < 4; p++) {
            int m0 = wr * 8 + 2 * p;
#pragma unroll
            for (int j = 0; j < 4; j++) {
                float o0, o1;
                unpack2(acc[p][j], o0, o1);
                o0 = fmaxf(o0 + bias0[j], 0.f);
                o1 = fmaxf(o1 + bias0[j], 0.f);
                *(u64*)&f3k[(tc * 4 + j) * S3 + m0] = pack2(o0, o1);
            }
        }
#undef LD3
#undef ST3
    }
    __syncthreads();

    // ================= phase L4: f4 = relu(f3 @ W4 + b4), K=128 ===============
    {
        const int tr4 = tid >> 3;         // 64 groups x 2 rows
        const int tc4 = tid & 7;          // 8 groups x 4 cols
        u64 acc[4] = {0ull, 0ull, 0ull, 0ull};
#pragma unroll 4
        for (int k = 0; k < 128; k++) {
            u64 a = *(const u64*)&f3k[k * S3 + tr4 * 2];
            float4 q = *(const float4*)&W4[k * 32 + tc4 * 4];
            float bv[4] = {q.x, q.y, q.z, q.w};
#pragma unroll
            for (int j = 0; j < 4; j++) fma2(acc[j], a, dup2(bv[j]));
        }
        float4 cb = *(const float4*)(b4 + tc4 * 4);
        float bias0[4] = {cb.x, cb.y, cb.z, cb.w};
#pragma unroll
        for (int j = 0; j < 4; j++) {
            float o0, o1;
            unpack2(acc[j], o0, o1);
            o0 = fmaxf(o0 + bias0[j], 0.f);
            o1 = fmaxf(o1 + bias0[j], 0.f);
            *(u64*)&f4k[(tc4 * 4 + j) * S3 + tr4 * 2] = pack2(o0, o1);
        }
        // loc / energy rows (scales folded into Wg)
        if (tid < 128) {
            int n = rowBase + tid;
            f4k[32 * S3 + tid] = loc[2 * n];
            f4k[33 * S3 + tid] = loc[2 * n + 1];
            f4k[34 * S3 + tid] = eng[n];
            f4k[35 * S3 + tid] = 0.f;
        }
    }
    __syncthreads();

    // ================= phase gx: gates = f4e @ Wg + bg, K=36 ==================
    for (int pc = 0; pc < 2; pc++) {
        u64 acc[4][8];
#pragma unroll
        for (int p = 0; p < 4; p++)
#pragma unroll
            for (int j = 0; j < 8; j++) acc[p][j] = 0ull;

#pragma unroll 4
        for (int k = 0; k < 36; k++) {
            const float* ar = f4k + k * S3 + wr * 8;
            u64 a0 = *(const u64*)(ar);
            u64 a1 = *(const u64*)(ar + 2);
            u64 a2 = *(const u64*)(ar + 4);
            u64 a3 = *(const u64*)(ar + 6);
            const float* bb = bsg + k * 516 + pc * 256 + tc * 8;
            float4 q0 = *(const float4*)(bb);
            float4 q1 = *(const float4*)(bb + 4);
            float bv[8] = {q0.x, q0.y, q0.z, q0.w, q1.x, q1.y, q1.z, q1.w};
#pragma unroll
            for (int j = 0; j < 8; j++) {
                u64 bd = dup2(bv[j]);
                fma2(acc[0][j], a0, bd); fma2(acc[1][j], a1, bd);
                fma2(acc[2][j], a2, bd); fma2(acc[3][j], a3, bd);
            }
        }
        float4 c0 = *(const float4*)(bg + pc * 256 + tc * 8);
        float4 c1 = *(const float4*)(bg + pc * 256 + tc * 8 + 4);
        float bias0[8] = {c0.x, c0.y, c0.z, c0.w, c1.x, c1.y, c1.z, c1.w};
#pragma unroll
        for (int p = 0; p < 4; p++) {
            int m0 = rowBase + wr * 8 + 2 * p;
            float o0[8], o1[8];
#pragma unroll
            for (int j = 0; j < 8; j++) {
                unpack2(acc[p][j], o0[j], o1[j]);
                o0[j] += bias0[j];
                o1[j] += bias0[j];
            }
            float* d0 = gx + (size_t)m0 * 512 + pc * 256 + tc * 8;
            float* d1 = gx + (size_t)(m0 + 1) * 512 + pc * 256 + tc * 8;
            *(float4*)(d0)     = make_float4(o0[0], o0[1], o0[2], o0[3]);
            *(float4*)(d0 + 4) = make_float4(o0[4], o0[5], o0[6], o0[7]);
            *(float4*)(d1)     = make_float4(o1[0], o1[1], o1[2], o1[3]);
            *(float4*)(d1 + 4) = make_float4(o1[4], o1[5], o1[6], o1[7]);
        }
    }
}

// ---------------------------------------------------------------------------
// LSTM: one CTA owns 16 batch rows, loops all T=128 steps locally (as R5).
// ---------------------------------------------------------------------------
#define LROWS 16

__global__ __launch_bounds__(512) void lstm_f32x2(
    const float* __restrict__ gx, const int* __restrict__ done,
    const float* __restrict__ h0, const float* __restrict__ c0,
    const float* __restrict__ Whh,
    const float* __restrict__ Wa, const float* __restrict__ ba,
    const float* __restrict__ Wc, const float* __restrict__ bc,
    float* __restrict__ out)
{
    __shared__ __align__(16) float h_s[HID][LROWS];   // 8 KB, transposed
    __shared__ float gs[4 * HID][17];                 // 34 KB, gate-major, padded

    const int tid = threadIdx.x;
    const int r0 = blockIdx.x * LROWS;

    float creg[4];
#pragma unroll
    for (int i = 0; i < 4; i++) {
        int e = tid + i * 512;
        int k = e >> 4, r = e & 15;
        h_s[k][r] = h0[(r0 + r) * HID + k];
        creg[i] = c0[(r0 + r) * HID + k];
    }
    __syncthreads();

    for (int t = 0; t < T_LEN; t++) {
#pragma unroll
        for (int i = 0; i < 4; i++) {
            int e = tid + i * 512;
            int k = e >> 4, r = e & 15;
            if (done[t * B_ENV + r0 + r]) { h_s[k][r] = 0.f; creg[i] = 0.f; }
        }
        __syncthreads();

        {
            const float* gp = gx + ((size_t)t * B_ENV + r0) * 512 + tid;
            u64 acc[8];
#pragma unroll
            for (int p = 0; p < 8; p++)
                acc[p] = pack2(gp[(size_t)(2 * p) * 512], gp[(size_t)(2 * p + 1) * 512]);

            const float4* w4 = (const float4*)(Whh + (size_t)tid * HID);
#pragma unroll 8
            for (int kk = 0; kk < 32; kk++) {
                float4 w = w4[kk];
                const float wv[4] = {w.x, w.y, w.z, w.w};
#pragma unroll
                for (int s = 0; s < 4; s++) {
                    int k = kk * 4 + s;
                    u64 wd = dup2(wv[s]);
                    const ulonglong2* hp = (const ulonglong2*)&h_s[k][0];
                    ulonglong2 hA = hp[0], hB = hp[1], hC = hp[2], hD = hp[3];
                    fma2(acc[0], wd, hA.x); fma2(acc[1], wd, hA.y);
                    fma2(acc[2], wd, hB.x); fma2(acc[3], wd, hB.y);
                    fma2(acc[4], wd, hC.x); fma2(acc[5], wd, hC.y);
                    fma2(acc[6], wd, hD.x); fma2(acc[7], wd, hD.y);
                }
            }
#pragma unroll
            for (int p = 0; p < 8; p++) {
                float lo, hi;
                unpack2(acc[p], lo, hi);
                gs[tid][2 * p] = lo;
                gs[tid][2 * p + 1] = hi;
            }
        }
        __syncthreads();

#pragma unroll
        for (int i = 0; i < 4; i++) {
            int e = tid + i * 512;
            int k = e >> 4, r = e & 15;
            float ig = gs[k][r];
            float fg = gs[HID + k][r];
            float gg = gs[2 * HID + k][r];
            float og = gs[3 * HID + k][r];
            float c = sigf(fg) * creg[i] + sigf(ig) * tanhf(gg);
            creg[i] = c;
            h_s[k][r] = sigf(og) * tanhf(c);
        }
        __syncthreads();

        if (tid < LROWS * (NA + 1)) {
            int r = tid / (NA + 1);
            int col = tid % (NA + 1);
            float s = (col < NA) ? ba[col] : bc[0];
            if (col < NA) {
#pragma unroll 8
                for (int k = 0; k < HID; k++) s += h_s[k][r] * Wa[k * NA + col];
            } else {
#pragma unroll 8
                for (int k = 0; k < HID; k++) s += h_s[k][r] * Wc[k];
            }
            out[((size_t)t * B_ENV + r0 + r) * (NA + 1) + col] = s;
        }
        __syncthreads();
    }
}

// ---------------------------------------------------------------------------
// Launch
// ---------------------------------------------------------------------------
extern "C" void kernel_launch(void* const* d_in, const int* in_sizes, int n_in,
                              void* d_out, int out_size)
{
    const float* image = (const float*)d_in[0];
    const float* location = (const float*)d_in[1];
    const float* energy = (const float*)d_in[2];
    const int*   done  = (const int*)d_in[3];
    const float* h0 = (const float*)d_in[4];
    const float* c0 = (const float*)d_in[5];
    const float* W1 = (const float*)d_in[6];
    const float* b1 = (const float*)d_in[7];
    const float* W2 = (const float*)d_in[8];
    const float* b2 = (const float*)d_in[9];
    const float* W3 = (const float*)d_in[10];
    const float* b3 = (const float*)d_in[11];
    const float* W4 = (const float*)d_in[12];
    const float* b4 = (const float*)d_in[13];
    const float* Wl = (const float*)d_in[14];
    const float* bl = (const float*)d_in[15];
    const float* We = (const float*)d_in[16];
    const float* be = (const float*)d_in[17];
    const float* Wih = (const float*)d_in[18];
    const float* Whh = (const float*)d_in[19];
    const float* bih = (const float*)d_in[20];
    const float* bhh = (const float*)d_in[21];
    const float* Wa = (const float*)d_in[22];
    const float* ba = (const float*)d_in[23];
    const float* Wc = (const float*)d_in[24];
    const float* bc = (const float*)d_in[25];
    float* out = (float*)d_out;

    float *pf2, *pgx, *pwg, *pbg;
    cudaGetSymbolAddress((void**)&pf2, g_f2);
    cudaGetSymbolAddress((void**)&pgx, g_gx);
    cudaGetSymbolAddress((void**)&pwg, g_wg);
    cudaGetSymbolAddress((void**)&pbg, g_bg);

    prep_wg<<<(36 * 512 + 255) / 256, 256>>>(Wih, Wl, We, pwg);
    prep_bg<<<2, 256>>>(Wih, bl, be, bih, bhh, pbg);

    // Dynamic SMEM: F12: 256*130 + 26*130 + 32*264 floats
    const int smem12 = (256 * S1 + 26 * S1 + 32 * 264) * 4;          // 179,912 B
    // F345: 128*130 + 36*130 + 32*130 + 32*132 + 36*516 floats
    const int smem345 = (128 * S3 + 36 * S3 + 32 * S3 + 32 * 132 + 36 * 516) * 4;  // 193,120 B
    cudaFuncSetAttribute(fused12, cudaFuncAttributeMaxDynamicSharedMemorySize, smem12);
    cudaFuncSetAttribute(fused345, cudaFuncAttributeMaxDynamicSharedMemorySize, smem345);

    const int MB = N_TOT / 128;   // 4096 row tiles

    fused12<<<MB, 512, smem12>>>(image, W1, b1, W2, b2, pf2);
    fused345<<<MB, 512, smem345>>>(pf2, location, energy, W3, b3, W4, b4, pwg, pbg, pgx);
    lstm_f32x2<<<B_ENV / LROWS, 512>>>(pgx, done, h0, c0, Whh, Wa, ba, Wc, bc, out);
}